// round 14
// baseline (speedup 1.0000x reference)
#include <cuda_runtime.h>
#include <float.h>
#include <math.h>

// Problem constants (from reference)
#define BEV_N   200          // BEV_H == BEV_W == 200
#define IMG_H   128
#define IMG_W   352
#define NCH     32
#define NB      2            // batch
#define NCAM    6            // cameras per batch
#define BNMAT   (NB*NCAM)    // 12 projection matrices
#define NPOS    (BEV_N*BEV_N)       // 40,000 positions (per batch)
#define THREADS 256
#define WARPS_PER_BLOCK (THREADS/32)         // 8
#define POS_PER_BLOCK  (THREADS/8)           // 32 (8 lanes per position)
#define NTASKS  (NPOS/4)                     // 10,000 warp-tasks
#define NBLOCKS (NTASKS/WARPS_PER_BLOCK)     // 1250
#define ROWSTRIDE (IMG_W * (NCH/4))
#define GRID_STEP 0.50251256281407031975f    // 100/199 rounded to fp32

// One fused kernel. Each thread owns ONE position but BOTH batches' cells.
// Work mapping: warp w of block b covers positions 4*(w*NBLOCKS + b)..+3.
//  - intra-warp: 4 CONSECUTIVE positions -> warp's gathers hit adjacent image
//    lines (locality R9 proved essential)
//  - inter-warp: warps of one block spread across the BEV -> balanced blocks
//  - 256 threads + minblocks 8 (regs<=32): 64-warp theoretical occupancy to
//    cover the ~250-cycle L2-hit latency that dominates the critical chain
__global__ __launch_bounds__(THREADS, 8) void ipm_fused_kernel(const float* __restrict__ images,
                                                               const float* __restrict__ Ks,
                                                               const float* __restrict__ RTs,
                                                               float* __restrict__ out) {
    __shared__ float  sP[BNMAT][9];
    __shared__ float4 sW[POS_PER_BLOCK][NB][NCAM];    // (w00,w01,w10,w11)
    __shared__ int    sBase[POS_PER_BLOCK][NB][NCAM]; // float4-index of im00 (pixel base)

    const int t = threadIdx.x;

    // ---------- Phase 0: projection matrices ----------
    if (t < BNMAT * 9) {
        const int m  = t / 9;
        const int e  = t - m * 9;
        const int r  = e / 3;
        const int ci = e - r * 3;
        const int c  = (ci == 2) ? 3 : ci;
        const float* K  = Ks  + m * 16 + r * 4;
        const float* RT = RTs + m * 16;
        sP[m][e] = K[0] * RT[c] + K[1] * RT[4 + c]
                 + K[2] * RT[8 + c] + K[3] * RT[12 + c];
    }
    __syncthreads();

    const int pos  = t >> 3;                           // local position slot 0..31
    const int sub  = t & 7;                            // lane-in-position / cam slot
    const int warp = t >> 5;                           // warp-in-block 0..7
    const int lpos = (t >> 3) & 3;                     // position-in-warp 0..3

    // Balanced warp-task mapping: 4 consecutive positions per warp,
    // warps of one block spread stride-NBLOCKS across the BEV.
    const int p = (warp * NBLOCKS + blockIdx.x) * 4 + lpos;

    const int i = p / BEV_N;
    const int j = p - i * BEV_N;
    // linspace(-50,50,200) in fp32 (<=1 ulp vs numpy's f64->f32; NO fp64 pipe)
    const float y = fmaf((float)i, GRID_STEP, -50.0f);
    const float x = fmaf((float)j, GRID_STEP, -50.0f);

    // ---------- Phase 1: project both batches + warp-local compaction ----------
    int nA, nB;
    {
        const int cam = sub;                           // cams 0..5 active, 6..7 idle
        bool vA = false, vB = false;
        float4 wA = make_float4(0.f, 0.f, 0.f, 0.f), wB = wA;
        int bA = 0, bB = 0;

        if (cam < NCAM) {
            #pragma unroll
            for (int ba = 0; ba < NB; ba++) {
                const int bn = ba * NCAM + cam;
                const float* P = sP[bn];
                const float pc0 = P[0] * y + P[1] * x + P[2];
                const float pc1 = P[3] * y + P[4] * x + P[5];
                const float pc2 = P[6] * y + P[7] * x + P[8];
                const float inv = 1.0f / (pc2 + 1e-7f);
                const float fx = pc0 * inv;
                const float fy = pc1 * inv;
                // Outside [0,W-1) x [0,H-1): clamped bilinear collapses => exact 0
                if (fx >= 0.0f && fx < (float)(IMG_W - 1) &&
                    fy >= 0.0f && fy < (float)(IMG_H - 1)) {
                    const float x0f = floorf(fx);
                    const float y0f = floorf(fy);
                    const float wx1 = fx - x0f, wx0 = 1.0f - wx1;
                    const float wy1 = fy - y0f, wy0 = 1.0f - wy1;
                    const float4 w = make_float4(wx0 * wy0, wx0 * wy1,
                                                 wx1 * wy0, wx1 * wy1);
                    const int base = ((bn * IMG_H + (int)y0f) * IMG_W + (int)x0f) * (NCH / 4);
                    if (ba == 0) { vA = true; wA = w; bA = base; }
                    else         { vB = true; wB = w; bB = base; }
                }
            }
        }

        const unsigned ballA = __ballot_sync(0xFFFFFFFFu, vA);
        const unsigned ballB = __ballot_sync(0xFFFFFFFFu, vB);
        const int laneBase   = (t & 31) & ~7;                   // first lane of 8-group
        const unsigned grpA  = (ballA >> laneBase) & 0xFFu;
        const unsigned grpB  = (ballB >> laneBase) & 0xFFu;
        const unsigned below = (1u << sub) - 1u;
        if (vA) {
            const int slot = __popc(grpA & below);              // cam-ordered slot
            sW[pos][0][slot] = wA;  sBase[pos][0][slot] = bA;
        }
        if (vB) {
            const int slot = __popc(grpB & below);
            sW[pos][1][slot] = wB;  sBase[pos][1][slot] = bB;
        }
        nA = (int)__popc(grpA);
        nB = (int)__popc(grpB);
    }
    __syncwarp();   // phase 1 writes / phase 2 reads are warp-local (same positions)

    // ---------- Phase 2: branchless paired sampling, max-reduce ----------
    // If every cam is valid the result is max over the 6 samples; otherwise some
    // cam contributes an exact 0 (clamp-collapsed weights), so seed with 0.
    float4 bestA = (nA == NCAM)
        ? make_float4(-FLT_MAX, -FLT_MAX, -FLT_MAX, -FLT_MAX)
        : make_float4(0.f, 0.f, 0.f, 0.f);
    float4 bestB = (nB == NCAM)
        ? make_float4(-FLT_MAX, -FLT_MAX, -FLT_MAX, -FLT_MAX)
        : make_float4(0.f, 0.f, 0.f, 0.f);

    const float4* __restrict__ img4 = (const float4*)images;
    const int nmax = (nA > nB) ? nA : nB;
    const float4 zero4 = make_float4(0.f, 0.f, 0.f, 0.f);

    #pragma unroll 1
    for (int k = 0; k < nmax; k++) {
        const bool okA = (k < nA), okB = (k < nB);
        const int  kA  = okA ? k : 0, kB = okB ? k : 0;
        // Inactive side: weight := 0 (exact-zero contribution), base := 0 (safe addr)
        float4 wA = sW[pos][0][kA];  int baA = okA ? sBase[pos][0][kA] : 0;
        float4 wB = sW[pos][1][kB];  int baB = okB ? sBase[pos][1][kB] : 0;
        if (!okA) wA = zero4;
        if (!okB) wB = zero4;

        const float4* pa = img4 + baA + sub;
        const float4* pb = img4 + baB + sub;
        // 8 independent loads in flight before any consume
        const float4 a00 = __ldg(pa);
        const float4 a10 = __ldg(pa + (NCH / 4));
        const float4 a01 = __ldg(pa + ROWSTRIDE);
        const float4 a11 = __ldg(pa + ROWSTRIDE + (NCH / 4));
        const float4 b00 = __ldg(pb);
        const float4 b10 = __ldg(pb + (NCH / 4));
        const float4 b01 = __ldg(pb + ROWSTRIDE);
        const float4 b11 = __ldg(pb + ROWSTRIDE + (NCH / 4));

        float4 v;
        v.x = wA.x * a00.x + wA.y * a01.x + wA.z * a10.x + wA.w * a11.x;
        v.y = wA.x * a00.y + wA.y * a01.y + wA.z * a10.y + wA.w * a11.y;
        v.z = wA.x * a00.z + wA.y * a01.z + wA.z * a10.z + wA.w * a11.z;
        v.w = wA.x * a00.w + wA.y * a01.w + wA.z * a10.w + wA.w * a11.w;
        bestA.x = fmaxf(bestA.x, v.x);
        bestA.y = fmaxf(bestA.y, v.y);
        bestA.z = fmaxf(bestA.z, v.z);
        bestA.w = fmaxf(bestA.w, v.w);

        v.x = wB.x * b00.x + wB.y * b01.x + wB.z * b10.x + wB.w * b11.x;
        v.y = wB.x * b00.y + wB.y * b01.y + wB.z * b10.y + wB.w * b11.y;
        v.z = wB.x * b00.z + wB.y * b01.z + wB.z * b10.z + wB.w * b11.z;
        v.w = wB.x * b00.w + wB.y * b01.w + wB.z * b10.w + wB.w * b11.w;
        bestB.x = fmaxf(bestB.x, v.x);
        bestB.y = fmaxf(bestB.y, v.y);
        bestB.z = fmaxf(bestB.z, v.z);
        bestB.w = fmaxf(bestB.w, v.w);
    }

    float4* out4 = (float4*)out;
    out4[(size_t)p * (NCH / 4) + sub]          = bestA;   // batch 0 cell
    out4[(size_t)(NPOS + p) * (NCH / 4) + sub] = bestB;   // batch 1 cell
}

extern "C" void kernel_launch(void* const* d_in, const int* in_sizes, int n_in,
                              void* d_out, int out_size) {
    const float* images = (const float*)d_in[0];
    const float* Ks     = (const float*)d_in[1];
    const float* RTs    = (const float*)d_in[2];
    float* out = (float*)d_out;

    ipm_fused_kernel<<<NBLOCKS, THREADS>>>(images, Ks, RTs, out);
}

// round 15
// speedup vs baseline: 1.0038x; 1.0038x over previous
#include <cuda_runtime.h>
#include <float.h>
#include <math.h>

// Problem constants (from reference)
#define BEV_N   200          // BEV_H == BEV_W == 200
#define IMG_H   128
#define IMG_W   352
#define NCH     32
#define NB      2            // batch
#define NCAM    6            // cameras per batch
#define BNMAT   (NB*NCAM)    // 12 projection matrices
#define NPOS    (BEV_N*BEV_N)       // 40,000 positions (per batch)
#define NTASKS  (NPOS/4)            // 10,000 warp-tasks (4 consecutive positions)
#define THREADS 256
#define WARPS_PER_BLOCK (THREADS/32)          // 8
#define NBLOCKS 592                            // 4 CTAs/SM * 148 SMs -> ONE wave
#define TOTAL_WARPS (NBLOCKS * WARPS_PER_BLOCK)   // 4736
#define ROWSTRIDE (IMG_W * (NCH/4))
#define GRID_STEP 0.50251256281407031975f     // 100/199 rounded to fp32

// One-wave warp-centric kernel: 592 blocks x 256 thr = 32 resident warps/SM for
// the whole kernel (no CTA turnover, no mini-wave transitions). Each warp
// grid-strides over ~2 tasks; a task = 4 CONSECUTIVE BEV positions (intra-warp
// gather locality) x both batches. Successive tasks of a warp are 18944
// positions apart -> per-warp total work ~ uniform (balance).
__global__ __launch_bounds__(THREADS) void ipm_fused_kernel(const float* __restrict__ images,
                                                            const float* __restrict__ Ks,
                                                            const float* __restrict__ RTs,
                                                            float* __restrict__ out) {
    __shared__ float  sP[BNMAT][9];
    __shared__ float4 sW[WARPS_PER_BLOCK * 4][NB][NCAM];    // per (warp,pos)
    __shared__ int    sBase[WARPS_PER_BLOCK * 4][NB][NCAM];

    const int t = threadIdx.x;

    // ---------- Phase 0 (once per block): projection matrices ----------
    if (t < BNMAT * 9) {
        const int m  = t / 9;
        const int e  = t - m * 9;
        const int r  = e / 3;
        const int ci = e - r * 3;
        const int c  = (ci == 2) ? 3 : ci;
        const float* K  = Ks  + m * 16 + r * 4;
        const float* RT = RTs + m * 16;
        sP[m][e] = K[0] * RT[c] + K[1] * RT[4 + c]
                 + K[2] * RT[8 + c] + K[3] * RT[12 + c];
    }
    __syncthreads();

    const int warpId = t >> 5;
    const int lane   = t & 31;
    const int lpos   = lane >> 3;                      // position-in-task 0..3
    const int sub    = lane & 7;                       // lane-in-position / cam slot
    const int wpos   = warpId * 4 + lpos;              // this thread's smem row
    const int gwarp  = blockIdx.x * WARPS_PER_BLOCK + warpId;

    const float4* __restrict__ img4 = (const float4*)images;
    float4* __restrict__ out4 = (float4*)out;
    const float4 zero4 = make_float4(0.f, 0.f, 0.f, 0.f);

    for (int task = gwarp; task < NTASKS; task += TOTAL_WARPS) {
        const int p = task * 4 + lpos;                 // global BEV position
        const int i = p / BEV_N;
        const int j = p - i * BEV_N;
        // linspace(-50,50,200) in fp32 (<=1 ulp vs numpy's f64->f32; NO fp64 pipe)
        const float y = fmaf((float)i, GRID_STEP, -50.0f);
        const float x = fmaf((float)j, GRID_STEP, -50.0f);

        // ---------- Phase 1: project both batches + warp-local compaction ----------
        int nA, nB;
        {
            const int cam = sub;                       // cams 0..5 active, 6..7 idle
            bool vA = false, vB = false;
            float4 wA = zero4, wB = zero4;
            int bA = 0, bB = 0;

            if (cam < NCAM) {
                #pragma unroll
                for (int ba = 0; ba < NB; ba++) {
                    const int bn = ba * NCAM + cam;
                    const float* P = sP[bn];
                    const float pc0 = P[0] * y + P[1] * x + P[2];
                    const float pc1 = P[3] * y + P[4] * x + P[5];
                    const float pc2 = P[6] * y + P[7] * x + P[8];
                    const float inv = 1.0f / (pc2 + 1e-7f);
                    const float fx = pc0 * inv;
                    const float fy = pc1 * inv;
                    // Outside [0,W-1) x [0,H-1): clamped bilinear collapses => exact 0
                    if (fx >= 0.0f && fx < (float)(IMG_W - 1) &&
                        fy >= 0.0f && fy < (float)(IMG_H - 1)) {
                        const float x0f = floorf(fx);
                        const float y0f = floorf(fy);
                        const float wx1 = fx - x0f, wx0 = 1.0f - wx1;
                        const float wy1 = fy - y0f, wy0 = 1.0f - wy1;
                        const float4 w = make_float4(wx0 * wy0, wx0 * wy1,
                                                     wx1 * wy0, wx1 * wy1);
                        const int base = ((bn * IMG_H + (int)y0f) * IMG_W + (int)x0f) * (NCH / 4);
                        if (ba == 0) { vA = true; wA = w; bA = base; }
                        else         { vB = true; wB = w; bB = base; }
                    }
                }
            }

            const unsigned ballA = __ballot_sync(0xFFFFFFFFu, vA);
            const unsigned ballB = __ballot_sync(0xFFFFFFFFu, vB);
            const int laneBase   = lane & ~7;                   // first lane of 8-group
            const unsigned grpA  = (ballA >> laneBase) & 0xFFu;
            const unsigned grpB  = (ballB >> laneBase) & 0xFFu;
            const unsigned below = (1u << sub) - 1u;
            if (vA) {
                const int slot = __popc(grpA & below);          // cam-ordered slot
                sW[wpos][0][slot] = wA;  sBase[wpos][0][slot] = bA;
            }
            if (vB) {
                const int slot = __popc(grpB & below);
                sW[wpos][1][slot] = wB;  sBase[wpos][1][slot] = bB;
            }
            nA = (int)__popc(grpA);
            nB = (int)__popc(grpB);
        }
        __syncwarp();   // phase 1 writes / phase 2 reads are warp-local

        // ---------- Phase 2: branchless paired sampling, max-reduce ----------
        // If every cam is valid the result is max over the 6 samples; otherwise
        // some cam contributes an exact 0 (clamp-collapsed weights) -> seed 0.
        float4 bestA = (nA == NCAM)
            ? make_float4(-FLT_MAX, -FLT_MAX, -FLT_MAX, -FLT_MAX)
            : zero4;
        float4 bestB = (nB == NCAM)
            ? make_float4(-FLT_MAX, -FLT_MAX, -FLT_MAX, -FLT_MAX)
            : zero4;

        const int nmax = (nA > nB) ? nA : nB;

        #pragma unroll 1
        for (int k = 0; k < nmax; k++) {
            const bool okA = (k < nA), okB = (k < nB);
            const int  kA  = okA ? k : 0, kB = okB ? k : 0;
            // Inactive side: weight := 0 (exact-zero contribution), base := 0 (safe)
            float4 wA = sW[wpos][0][kA];  int baA = okA ? sBase[wpos][0][kA] : 0;
            float4 wB = sW[wpos][1][kB];  int baB = okB ? sBase[wpos][1][kB] : 0;
            if (!okA) wA = zero4;
            if (!okB) wB = zero4;

            const float4* pa = img4 + baA + sub;
            const float4* pb = img4 + baB + sub;
            // 8 independent loads in flight before any consume
            const float4 a00 = __ldg(pa);
            const float4 a10 = __ldg(pa + (NCH / 4));
            const float4 a01 = __ldg(pa + ROWSTRIDE);
            const float4 a11 = __ldg(pa + ROWSTRIDE + (NCH / 4));
            const float4 b00 = __ldg(pb);
            const float4 b10 = __ldg(pb + (NCH / 4));
            const float4 b01 = __ldg(pb + ROWSTRIDE);
            const float4 b11 = __ldg(pb + ROWSTRIDE + (NCH / 4));

            float4 v;
            v.x = wA.x * a00.x + wA.y * a01.x + wA.z * a10.x + wA.w * a11.x;
            v.y = wA.x * a00.y + wA.y * a01.y + wA.z * a10.y + wA.w * a11.y;
            v.z = wA.x * a00.z + wA.y * a01.z + wA.z * a10.z + wA.w * a11.z;
            v.w = wA.x * a00.w + wA.y * a01.w + wA.z * a10.w + wA.w * a11.w;
            bestA.x = fmaxf(bestA.x, v.x);
            bestA.y = fmaxf(bestA.y, v.y);
            bestA.z = fmaxf(bestA.z, v.z);
            bestA.w = fmaxf(bestA.w, v.w);

            v.x = wB.x * b00.x + wB.y * b01.x + wB.z * b10.x + wB.w * b11.x;
            v.y = wB.x * b00.y + wB.y * b01.y + wB.z * b10.y + wB.w * b11.y;
            v.z = wB.x * b00.z + wB.y * b01.z + wB.z * b10.z + wB.w * b11.z;
            v.w = wB.x * b00.w + wB.y * b01.w + wB.z * b10.w + wB.w * b11.w;
            bestB.x = fmaxf(bestB.x, v.x);
            bestB.y = fmaxf(bestB.y, v.y);
            bestB.z = fmaxf(bestB.z, v.z);
            bestB.w = fmaxf(bestB.w, v.w);
        }

        out4[(size_t)p * (NCH / 4) + sub]          = bestA;   // batch 0 cell
        out4[(size_t)(NPOS + p) * (NCH / 4) + sub] = bestB;   // batch 1 cell

        __syncwarp();   // protect smem slots from next iteration's overwrite
    }
}

extern "C" void kernel_launch(void* const* d_in, const int* in_sizes, int n_in,
                              void* d_out, int out_size) {
    const float* images = (const float*)d_in[0];
    const float* Ks     = (const float*)d_in[1];
    const float* RTs    = (const float*)d_in[2];
    float* out = (float*)d_out;

    ipm_fused_kernel<<<NBLOCKS, THREADS>>>(images, Ks, RTs, out);
}

// round 16
// speedup vs baseline: 1.3145x; 1.3096x over previous
#include <cuda_runtime.h>
#include <float.h>
#include <math.h>

// Problem constants (from reference)
#define BEV_N   200          // BEV_H == BEV_W == 200
#define IMG_H   128
#define IMG_W   352
#define NCH     32
#define NB      2            // batch
#define NCAM    6            // cameras per batch
#define BNMAT   (NB*NCAM)    // 12 projection matrices
#define NCELL   (NB*BEV_N*BEV_N)    // 80,000 cells (batch included)
#define CELLS_PER_BLOCK 32          // 256 threads / 8 lanes-per-cell
#define ROWSTRIDE (IMG_W * (NCH/4))
#define GRID_STEP 0.50251256281407031975f   // 100/199 rounded to fp32

// R7 skeleton (best measured kernel) with instruction-count reduction:
//  - shuffle-based compaction: valid cams' {weights, base} stay in the
//    computing lane's registers; consumers fetch via __shfl_sync over the
//    group's valid-bitmask (no smem round-trip, no slot math, no syncwarp)
//  - rcp.approx.f32 instead of IEEE division (1 MUFU vs ~8 instrs)
//  - per-lane P coefficients loaded from smem once into registers
__global__ __launch_bounds__(256) void ipm_fused_kernel(const float* __restrict__ images,
                                                        const float* __restrict__ Ks,
                                                        const float* __restrict__ RTs,
                                                        float* __restrict__ out) {
    __shared__ float sP[BNMAT][9];

    const int t = threadIdx.x;

    // ---------- Phase 0: projection matrices P = rows 0..2 of K@RT, cols {0,1,3} ----------
    if (t < BNMAT * 9) {
        const int m  = t / 9;
        const int e  = t - m * 9;
        const int r  = e / 3;
        const int ci = e - r * 3;
        const int c  = (ci == 2) ? 3 : ci;
        const float* K  = Ks  + m * 16 + r * 4;
        const float* RT = RTs + m * 16;
        sP[m][e] = K[0] * RT[c] + K[1] * RT[4 + c]
                 + K[2] * RT[8 + c] + K[3] * RT[12 + c];
    }
    __syncthreads();

    const int cell = blockIdx.x * CELLS_PER_BLOCK + (t >> 3);   // grid exact: 2500*32
    const int sub  = t & 7;                                     // lane-in-cell / cam
    const int laneBase = (t & 31) & ~7;                         // first lane of 8-group

    const int b   = cell / (BEV_N * BEV_N);
    const int rem = cell - b * (BEV_N * BEV_N);
    const int i   = rem / BEV_N;
    const int j   = rem - i * BEV_N;
    // linspace(-50,50,200) in fp32 (<=1 ulp vs numpy's f64->f32; NO fp64 pipe)
    const float y = fmaf((float)i, GRID_STEP, -50.0f);
    const float x = fmaf((float)j, GRID_STEP, -50.0f);

    // ---------- Phase 1: this lane projects its camera (cam = sub) ----------
    bool valid = false;
    float w0 = 0.f, w1 = 0.f, w2 = 0.f, w3 = 0.f;   // bilinear weights
    float baseF = 0.f;                               // base idx carried as float for shfl
    if (sub < NCAM) {
        const int bn = b * NCAM + sub;
        const float p0 = sP[bn][0], p1 = sP[bn][1], p2 = sP[bn][2];
        const float p3 = sP[bn][3], p4 = sP[bn][4], p5 = sP[bn][5];
        const float p6 = sP[bn][6], p7 = sP[bn][7], p8 = sP[bn][8];
        const float pc0 = p0 * y + p1 * x + p2;
        const float pc1 = p3 * y + p4 * x + p5;
        const float pc2 = p6 * y + p7 * x + p8;
        float inv;
        asm("rcp.approx.f32 %0, %1;" : "=f"(inv) : "f"(pc2 + 1e-7f));
        const float fx = pc0 * inv;
        const float fy = pc1 * inv;
        // Outside [0,W-1) x [0,H-1): clamped bilinear collapses => exact 0
        if (fx >= 0.0f && fx < (float)(IMG_W - 1) &&
            fy >= 0.0f && fy < (float)(IMG_H - 1)) {
            valid = true;
            const float x0f = floorf(fx);
            const float y0f = floorf(fy);
            const float wx1 = fx - x0f, wx0 = 1.0f - wx1;
            const float wy1 = fy - y0f, wy0 = 1.0f - wy1;
            w0 = wx0 * wy0;  w1 = wx0 * wy1;
            w2 = wx1 * wy0;  w3 = wx1 * wy1;
            const int base = ((b * NCAM + sub) * IMG_H + (int)y0f) * IMG_W * (NCH / 4)
                           + (int)x0f * (NCH / 4);
            baseF = __int_as_float(base);
        }
    }

    const unsigned ball = __ballot_sync(0xFFFFFFFFu, valid);
    unsigned m = (ball >> laneBase) & 0x3Fu;          // this group's valid-cam mask
    const int n = (int)__popc(m);

    // ---------- Phase 2: iterate valid cams via shuffle, max-reduce ----------
    // If every cam is valid the result is max over the 6 samples; otherwise some
    // cam contributes an exact 0 (clamp-collapsed weights), so seed with 0.
    float4 best = (n == NCAM)
        ? make_float4(-FLT_MAX, -FLT_MAX, -FLT_MAX, -FLT_MAX)
        : make_float4(0.f, 0.f, 0.f, 0.f);

    const float4* __restrict__ img4 = (const float4*)images;

    while (m) {
        const int cam = __ffs(m) - 1;
        m &= m - 1;
        const int src = laneBase + cam;
        const float cw0 = __shfl_sync(0xFFFFFFFFu, w0, src);
        const float cw1 = __shfl_sync(0xFFFFFFFFu, w1, src);
        const float cw2 = __shfl_sync(0xFFFFFFFFu, w2, src);
        const float cw3 = __shfl_sync(0xFFFFFFFFu, w3, src);
        const int  base = __float_as_int(__shfl_sync(0xFFFFFFFFu, baseF, src));

        const float4* p = img4 + base + sub;
        const float4 v00 = __ldg(p);
        const float4 v10 = __ldg(p + (NCH / 4));
        const float4 v01 = __ldg(p + ROWSTRIDE);
        const float4 v11 = __ldg(p + ROWSTRIDE + (NCH / 4));

        float4 v;
        v.x = cw0 * v00.x + cw1 * v01.x + cw2 * v10.x + cw3 * v11.x;
        v.y = cw0 * v00.y + cw1 * v01.y + cw2 * v10.y + cw3 * v11.y;
        v.z = cw0 * v00.z + cw1 * v01.z + cw2 * v10.z + cw3 * v11.z;
        v.w = cw0 * v00.w + cw1 * v01.w + cw2 * v10.w + cw3 * v11.w;

        best.x = fmaxf(best.x, v.x);
        best.y = fmaxf(best.y, v.y);
        best.z = fmaxf(best.z, v.z);
        best.w = fmaxf(best.w, v.w);
    }

    ((float4*)out)[(size_t)cell * (NCH / 4) + sub] = best;
}

extern "C" void kernel_launch(void* const* d_in, const int* in_sizes, int n_in,
                              void* d_out, int out_size) {
    const float* images = (const float*)d_in[0];
    const float* Ks     = (const float*)d_in[1];
    const float* RTs    = (const float*)d_in[2];
    float* out = (float*)d_out;

    const int nblocks = NCELL / CELLS_PER_BLOCK;   // 80000/32 = 2500, exact
    ipm_fused_kernel<<<nblocks, 256>>>(images, Ks, RTs, out);
}